// round 5
// baseline (speedup 1.0000x reference)
#include <cuda_runtime.h>
#include <cuda_bf16.h>
#include <cstdint>

#define NROWS 262144
#define DDIM  128

typedef unsigned long long u64;
typedef unsigned int u32;

#if defined(__CUDA_ARCH__) && defined(__CUDA_ARCH_FEAT_SM103_ALL)
#define HAS_TCGEN05 1
#else
#define HAS_TCGEN05 0
#endif

// ---------------- device scratch (no allocations allowed) ----------------
__device__ float g_e[NROWS];
__device__ float g_sp[NROWS];
__device__ float g_expw[NROWS];
__device__ float g_S_part[2048];
__device__ float g_sumeE_part[2048 * 128];
__device__ float g_S;
__device__ float g_Cvec[128];
__device__ float g_bias[128];
__device__ __align__(16) float g_Wt[128 * 256];  // Wt[k][n] fp32 (FFMA2 path)
__device__ __align__(16) u32 g_Bhi_img[16384];   // pre-swizzled bf16 hi image (tcgen05 path)
__device__ __align__(16) u32 g_Blo_img[16384];   // pre-swizzled bf16 lo image
__device__ float g_gePart[2048 * 128];
__device__ float g_esumPart[2048];
__device__ float g_ge2[32 * 128];
__device__ float g_esum2[32];
__device__ float g_total;

// ---------------- generic helpers ----------------
#define SMEM_SW128(o) ((o) ^ (((o) >> 3) & 0x70))

__device__ __forceinline__ u64 pack2(float x, float y) {
    u64 r;
    asm("mov.b64 %0, {%1, %2};" : "=l"(r) : "f"(x), "f"(y));
    return r;
}
__device__ __forceinline__ void fma2(u64 &d, u64 a, u64 b) {
    asm("fma.rn.f32x2 %0, %1, %2, %0;" : "+l"(d) : "l"(a), "l"(b));
}
__device__ __forceinline__ void unpack2(u64 v, float &x, float &y) {
    asm("mov.b64 {%0, %1}, %2;" : "=f"(x), "=f"(y) : "l"(v));
}

// ---------------- smem layout for k3 (shared by both paths) ----------------
#define FF_AS     0          // 128x128 fp32  (65536 B)
#define FF_BS     65536      // 128x256 fp32  (131072 B)
#define A_HI_OFF  0          // tcgen05 path: bf16 images
#define A_LO_OFF  32768
#define B_HI_OFF  65536
#define B_LO_OFF  131072
#define TMEMPTR_OFF 196608
#define MBAR_OFF    196616
#define CVEC_OFF    196640
#define BIAS_OFF    197152
#define WVC_OFF     197664
#define ESM_OFF     198176
#define SPM_OFF     198688
#define WROW_OFF    199200
#define RED_OFF     199712   // up to 8192 B
#define SM3_BYTES   208896

// ---------------- kernel 0: build Wt[k][n] = [W1^T | W2^T] (fp32) ----------------
__global__ void k0_wt(const float* __restrict__ W1, const float* __restrict__ W2) {
    int idx = blockIdx.x * 256 + threadIdx.x;   // 0..32767
    int k = idx >> 8;
    int n = idx & 255;
    g_Wt[idx] = (n < 128) ? W1[n * 128 + k] : W2[(n - 128) * 128 + k];
}

// ---------------- kernel 0b: pre-swizzled bf16 hi/lo B image (tcgen05 path) ----------------
// B logical: [n=256 rows][k=128 cols] K-major. Atom = 8 rows x 64 bf16 (1024B),
// atom_offset = (n>>3) + (k>>6)*32, + SW128 swizzle within atom rows.
__global__ void k0b_bimg(const float* __restrict__ W1, const float* __restrict__ W2) {
    int idx = blockIdx.x * 256 + threadIdx.x;    // 0..16383 bf16x2 words
    int n = idx >> 6;
    int kp = (idx & 63) * 2;
    const float* src = (n < 128) ? (W1 + n * 128) : (W2 + (n - 128) * 128);
    float x0 = src[kp], x1 = src[kp + 1];
    __nv_bfloat16 h0 = __float2bfloat16_rn(x0);
    __nv_bfloat16 h1 = __float2bfloat16_rn(x1);
    __nv_bfloat162 hw = __nv_bfloat162(h0, h1);
    __nv_bfloat162 lw = __floats2bfloat162_rn(x0 - __bfloat162float(h0),
                                              x1 - __bfloat162float(h1));
    int off = ((n >> 3) + (kp >> 6) * 32) * 1024 + (n & 7) * 128 + (kp & 63) * 2;
    int sw = SMEM_SW128(off);
    g_Bhi_img[sw >> 2] = *(u32*)&hw;
    g_Blo_img[sw >> 2] = *(u32*)&lw;
}

// ---------------- kernel 1: sp, s->e, partial S, partial sum_eE (smem-staged) ----------------
#define K1_STRIDE 129
#define K1_SVW    (128 * K1_STRIDE)
#define K1_EXP    (K1_SVW + 256)
#define K1_FLOATS (K1_EXP + 128)
#define K1_BYTES  (K1_FLOATS * 4)

__global__ __launch_bounds__(128) void k1_pass1(const float* __restrict__ E,
                                                const float* __restrict__ v,
                                                const float* __restrict__ wpa,
                                                const float* __restrict__ bpa) {
    extern __shared__ float s1[];
    float*  Es  = s1;
    float2* svw = (float2*)(s1 + K1_SVW);
    float*  es  = s1 + K1_EXP;

    int t = threadIdx.x;
    int rowbase = blockIdx.x * 128;
    const float4* E4 = (const float4*)E + rowbase * 32;

    #pragma unroll
    for (int i = 0; i < 32; i++) {
        int g4 = t + i * 128;
        int r = g4 >> 5, c4 = g4 & 31;
        float4 val = E4[g4];
        Es[(c4 * 4 + 0) * K1_STRIDE + r] = val.x;
        Es[(c4 * 4 + 1) * K1_STRIDE + r] = val.y;
        Es[(c4 * 4 + 2) * K1_STRIDE + r] = val.z;
        Es[(c4 * 4 + 3) * K1_STRIDE + r] = val.w;
    }
    svw[t] = make_float2(wpa[t], v[t]);
    __syncthreads();

    float sp = 0.f, s = 0.f;
    #pragma unroll 8
    for (int k = 0; k < 128; k++) {
        float ev = Es[k * K1_STRIDE + t];
        float2 c = svw[k];
        s  = fmaf(ev, c.x, s);
        sp = fmaf(ev, c.y, sp);
    }
    s += bpa[0];
    float e = expf(s);       // softmax shift-invariant; exponents tiny
    g_sp[rowbase + t] = sp;
    g_e[rowbase + t]  = e;
    es[t] = e;
    __syncthreads();

    float acc = 0.f;
    #pragma unroll 8
    for (int r = 0; r < 128; r++) acc = fmaf(es[r], Es[t * K1_STRIDE + r], acc);
    g_sumeE_part[blockIdx.x * 128 + t] = acc;

    if (t < 32) {
        float t4 = es[t] + es[t + 32] + es[t + 64] + es[t + 96];
        #pragma unroll
        for (int off = 16; off; off >>= 1) t4 += __shfl_xor_sync(0xffffffffu, t4, off);
        if (t == 0) g_S_part[blockIdx.x] = t4;
    }
}

// ---------------- kernel 2: reduce S & sum_eE; Cvec = W2 @ sum_eE; bias ----------------
__global__ void k2_reduce(const float* __restrict__ W2,
                          const float* __restrict__ b_c1,
                          const float* __restrict__ b_c2) {
    __shared__ float red[256];
    __shared__ float se[128];
    int tid = threadIdx.x;
    float s = 0.f;
    for (int b = tid; b < 2048; b += 256) s += g_S_part[b];
    red[tid] = s;
    __syncthreads();
    for (int off = 128; off > 0; off >>= 1) {
        if (tid < off) red[tid] += red[tid + off];
        __syncthreads();
    }
    float Stot = red[0];
    __syncthreads();
    int d = tid & 127, h = tid >> 7;
    float p = 0.f;
    for (int b = h; b < 2048; b += 2) p += g_sumeE_part[b * 128 + d];
    red[tid] = p;
    __syncthreads();
    if (tid < 128) se[tid] = red[tid] + red[tid + 128];
    __syncthreads();
    if (tid < 128) {
        float c = 0.f;
        #pragma unroll 8
        for (int k = 0; k < 128; k++) c += W2[tid * 128 + k] * se[k];
        g_Cvec[tid] = c;
        g_bias[tid] = b_c1[tid] + b_c2[tid];
    }
    if (tid == 0) g_S = Stot;
}

// ---------------- tcgen05 helpers (only compiled on 103a feature pass) ----------------
#if HAS_TCGEN05
__device__ __forceinline__ u32 smem_to_u32(const void* p) {
    u32 a;
    asm("{ .reg .u64 t; cvta.to.shared.u64 t, %1; cvt.u32.u64 %0, t; }" : "=r"(a) : "l"(p));
    return a;
}
__device__ __forceinline__ u32 elect_one_pred() {
    u32 pred;
    asm volatile("{ .reg .pred p; elect.sync _|p, 0xFFFFFFFF; selp.b32 %0, 1, 0, p; }" : "=r"(pred));
    return pred;
}
static constexpr u64 SMEM_DESC_BASE_SW128 =
    (u64(2) << 61) | (u64(1) << 46) | (u64(64) << 32) | (u64(1) << 16);
#define MAKE_SMEM_DESC(a) (SMEM_DESC_BASE_SW128 | ((u64)((a) >> 4) & 0x3FFF))

#define TCGEN05_ALLOC(sa, n) \
    asm volatile("tcgen05.alloc.cta_group::1.sync.aligned.shared::cta.b32 [%0], %1;" \
                 :: "r"((u32)(sa)), "r"((u32)(n)) : "memory")
#define TCGEN05_DEALLOC(t, n) \
    asm volatile("tcgen05.dealloc.cta_group::1.sync.aligned.b32 %0, %1;" :: "r"(t), "r"((u32)(n)))
#define TCGEN05_COMMIT(mb) \
    asm volatile("tcgen05.commit.cta_group::1.mbarrier::arrive::one.shared::cluster.b64 [%0];" \
                 :: "r"((u32)(mb)) : "memory")
#define TCGEN05_WAIT_LD()  asm volatile("tcgen05.wait::ld.sync.aligned;" ::: "memory")
#define TCGEN05_FENCE_AFTER() asm volatile("tcgen05.fence::after_thread_sync;" ::: "memory")
#define TCGEN05_FENCE_BEFORE() asm volatile("tcgen05.fence::before_thread_sync;" ::: "memory")
#define MBARRIER_INIT(mb, c) \
    asm volatile("mbarrier.init.shared.b64 [%0], %1;" :: "r"((u32)(mb)), "r"((u32)(c)) : "memory")
#define MBARRIER_WAIT_PARITY(mb, ph) do { \
    u32 _mb = (u32)(mb); u32 _p = (u32)(ph); u32 _done; \
    asm volatile("{ .reg .pred p; mbarrier.try_wait.parity.acquire.cta.shared::cta.b64 p, [%1], %2; selp.b32 %0, 1, 0, p; }" \
        : "=r"(_done) : "r"(_mb), "r"(_p) : "memory"); \
    if (!_done) { \
        asm volatile("{ .reg .pred P1; WL_%=: mbarrier.try_wait.parity.acquire.cta.shared::cta.b64 P1, [%0], %1, 0x989680; @P1 bra.uni WD_%=; bra.uni WL_%=; WD_%=: }" \
            :: "r"(_mb), "r"(_p) : "memory"); \
    } \
} while (0)
#define TCGEN05_LD_32X32B_X32(r, ta) \
    asm volatile("tcgen05.ld.sync.aligned.32x32b.x32.b32 " \
        "{%0, %1, %2, %3, %4, %5, %6, %7, %8, %9, %10, %11, %12, %13, %14, %15, " \
        " %16, %17, %18, %19, %20, %21, %22, %23, %24, %25, %26, %27, %28, %29, %30, %31}, [%32];" \
        : "=r"((r)[0]),  "=r"((r)[1]),  "=r"((r)[2]),  "=r"((r)[3]), \
          "=r"((r)[4]),  "=r"((r)[5]),  "=r"((r)[6]),  "=r"((r)[7]), \
          "=r"((r)[8]),  "=r"((r)[9]),  "=r"((r)[10]), "=r"((r)[11]), \
          "=r"((r)[12]), "=r"((r)[13]), "=r"((r)[14]), "=r"((r)[15]), \
          "=r"((r)[16]), "=r"((r)[17]), "=r"((r)[18]), "=r"((r)[19]), \
          "=r"((r)[20]), "=r"((r)[21]), "=r"((r)[22]), "=r"((r)[23]), \
          "=r"((r)[24]), "=r"((r)[25]), "=r"((r)[26]), "=r"((r)[27]), \
          "=r"((r)[28]), "=r"((r)[29]), "=r"((r)[30]), "=r"((r)[31]) \
        : "r"(ta))

__device__ __forceinline__ void mma_f16_ss(u32 d, u64 ad, u64 bd, u32 idesc, bool en) {
    u32 e = en ? 1u : 0u;
    asm volatile(
        "{\n\t.reg .pred p;\n\tsetp.ne.u32 p, %4, 0;\n\t"
        "tcgen05.mma.cta_group::1.kind::f16 [%0], %1, %2, %3, {%5, %5, %5, %5}, p;\n\t}"
        :: "r"(d), "l"(ad), "l"(bd), "r"(idesc), "r"(e), "r"(0u) : "memory");
}
// idesc: dtype F32, a/b BF16, N=128, M=128
static constexpr u32 MMA_IDESC_N128 =
    (1u << 4) | (1u << 7) | (1u << 10) | (16u << 17) | (8u << 24);
#endif  // HAS_TCGEN05

// ---------------- kernel 3: main fused GEMM + PI + logits + block partials ----------------
// 2048 blocks x 512 threads; 128 rows/block; N=256; K=128.
__global__ __launch_bounds__(512, 1)
void k3_main(const float* __restrict__ E,
             const float* __restrict__ wvc,
             const float* __restrict__ bvcp) {
    extern __shared__ char smc[];
    float* cvecS = (float*)(smc + CVEC_OFF);
    float* biasS = (float*)(smc + BIAS_OFF);
    float* wvcS  = (float*)(smc + WVC_OFF);
    float* esm   = (float*)(smc + ESM_OFF);
    float* spm   = (float*)(smc + SPM_OFF);
    float* wrow  = (float*)(smc + WROW_OFF);
    float* red   = (float*)(smc + RED_OFF);

    int tid = threadIdx.x;
    int lane = tid & 31;
    int wid = tid >> 5;             // 0..15
    int rowbase = blockIdx.x * 128;

#if HAS_TCGEN05
    // ======================= tcgen05 path =======================
    u32 smem_base = smem_to_u32(smc);
    if (wid == 0) TCGEN05_ALLOC(smem_base + TMEMPTR_OFF, 256);
    if (tid == 0) MBARRIER_INIT(smem_base + MBAR_OFF, 1);

    {   // copy pre-swizzled B images
        const float4* bh = (const float4*)g_Bhi_img;
        const float4* bl = (const float4*)g_Blo_img;
        float4* dh = (float4*)(smc + B_HI_OFF);
        float4* dl = (float4*)(smc + B_LO_OFF);
        #pragma unroll
        for (int i = 0; i < 8; i++) {
            dh[tid + i * 512] = bh[tid + i * 512];
            dl[tid + i * 512] = bl[tid + i * 512];
        }
    }
    {   // load E tile, split bf16 hi/lo, store swizzled (atoms: (r>>3)+(c>>6)*16)
        const float4* E4 = (const float4*)E + rowbase * 32;
        #pragma unroll
        for (int i = 0; i < 8; i++) {
            int g4 = tid + i * 512;
            int r = g4 >> 5;
            int c = (g4 & 31) * 4;
            float4 x = E4[g4];
            __nv_bfloat16 h0 = __float2bfloat16_rn(x.x);
            __nv_bfloat16 h1 = __float2bfloat16_rn(x.y);
            __nv_bfloat16 h2 = __float2bfloat16_rn(x.z);
            __nv_bfloat16 h3 = __float2bfloat16_rn(x.w);
            __nv_bfloat162 hw0 = __nv_bfloat162(h0, h1);
            __nv_bfloat162 hw1 = __nv_bfloat162(h2, h3);
            __nv_bfloat162 lw0 = __floats2bfloat162_rn(x.x - __bfloat162float(h0),
                                                       x.y - __bfloat162float(h1));
            __nv_bfloat162 lw1 = __floats2bfloat162_rn(x.z - __bfloat162float(h2),
                                                       x.w - __bfloat162float(h3));
            int off = ((r >> 3) + (c >> 6) * 16) * 1024 + (r & 7) * 128 + (c & 63) * 2;
            int sw = SMEM_SW128(off);
            u64 hp = (u64)(*(u32*)&hw0) | ((u64)(*(u32*)&hw1) << 32);
            u64 lp = (u64)(*(u32*)&lw0) | ((u64)(*(u32*)&lw1) << 32);
            *(u64*)(smc + A_HI_OFF + sw) = hp;
            *(u64*)(smc + A_LO_OFF + sw) = lp;
        }
    }
    if (tid < 128) {
        cvecS[tid] = g_Cvec[tid];
        biasS[tid] = g_bias[tid];
        wvcS[tid]  = wvc[tid];
        esm[tid]   = g_e[rowbase + tid];
        spm[tid]   = g_sp[rowbase + tid];
    }
    float Sv  = g_S;
    float bvc = bvcp[0];

    asm volatile("fence.proxy.async.shared::cta;" ::: "memory");
    __syncthreads();
    u32 tmem_base;
    asm volatile("ld.shared.b32 %0, [%1];" : "=r"(tmem_base) : "r"(smem_base + TMEMPTR_OFF));

    if (wid == 0) {
        if (elect_one_pred()) {
            u64 adh = MAKE_SMEM_DESC(smem_base + A_HI_OFF);
            u64 adl = MAKE_SMEM_DESC(smem_base + A_LO_OFF);
            u64 bdh = MAKE_SMEM_DESC(smem_base + B_HI_OFF);
            u64 bdl = MAKE_SMEM_DESC(smem_base + B_LO_OFF);
            const u64 aoff[8] = {0, 2, 4, 6, 1024, 1026, 1028, 1030};
            const u64 boff[8] = {0, 2, 4, 6, 2048, 2050, 2052, 2054};
            #pragma unroll
            for (int nh = 0; nh < 2; nh++) {
                u32 dtm = tmem_base + nh * 128;
                u64 bh = bdh + nh * 1024;
                u64 bl = bdl + nh * 1024;
                #pragma unroll
                for (int s = 0; s < 8; s++)
                    mma_f16_ss(dtm, adh + aoff[s], bh + boff[s], MMA_IDESC_N128, s > 0);
                #pragma unroll
                for (int s = 0; s < 8; s++)
                    mma_f16_ss(dtm, adh + aoff[s], bl + boff[s], MMA_IDESC_N128, true);
                #pragma unroll
                for (int s = 0; s < 8; s++)
                    mma_f16_ss(dtm, adl + aoff[s], bh + boff[s], MMA_IDESC_N128, true);
            }
            TCGEN05_COMMIT(smem_base + MBAR_OFF);
        }
    }

    MBARRIER_WAIT_PARITY(smem_base + MBAR_OFF, 0);
    TCGEN05_FENCE_AFTER();

    if (wid < 4) {
        int r = wid * 32 + lane;
        float e_i = esm[r];
        float inv = 1.0f / (Sv - e_i);
        float pi = 0.f;
        #pragma unroll
        for (int q = 0; q < 4; q++) {
            u32 ra[32], rb[32];
            TCGEN05_LD_32X32B_X32(ra, tmem_base + q * 32);
            TCGEN05_LD_32X32B_X32(rb, tmem_base + 128 + q * 32);
            TCGEN05_WAIT_LD();
            #pragma unroll
            for (int jj = 0; jj < 32; jj++) {
                int j = q * 32 + jj;
                float a  = __uint_as_float(ra[jj]);
                float bb = __uint_as_float(rb[jj]);
                float hv = a + (cvecS[j] - e_i * bb) * inv + biasS[j];
                pi += fmaxf(hv, 0.f) * wvcS[j];
            }
        }
        TCGEN05_FENCE_BEFORE();
        float lg = spm[r] + pi + bvc;
        float wv = expf(lg);
        wrow[r] = wv;
        g_expw[rowbase + r] = wv;
    }
    __syncthreads();

    // block partials from reconstructed E (hi+lo): warp wid handles rows wid*8..+7
    {
        float a0 = 0.f, a1 = 0.f, a2 = 0.f, a3 = 0.f;
        #pragma unroll
        for (int rr = 0; rr < 8; rr++) {
            int r = wid * 8 + rr;
            float wv = wrow[r];
            int base = (r >> 3) * 1024 + (r & 7) * 128;
            int o0 = SMEM_SW128(base + lane * 4);
            int o1 = SMEM_SW128(base + 16 * 1024 + lane * 4);
            float2 h0 = __bfloat1622float2(*(const __nv_bfloat162*)(smc + A_HI_OFF + o0));
            float2 l0 = __bfloat1622float2(*(const __nv_bfloat162*)(smc + A_LO_OFF + o0));
            float2 h1 = __bfloat1622float2(*(const __nv_bfloat162*)(smc + A_HI_OFF + o1));
            float2 l1 = __bfloat1622float2(*(const __nv_bfloat162*)(smc + A_LO_OFF + o1));
            a0 = fmaf(wv, h0.x + l0.x, a0);
            a1 = fmaf(wv, h0.y + l0.y, a1);
            a2 = fmaf(wv, h1.x + l1.x, a2);
            a3 = fmaf(wv, h1.y + l1.y, a3);
        }
        float2* r2 = (float2*)red;
        r2[wid * 64 + lane]      = make_float2(a0, a1);   // cols 2l, 2l+1
        r2[wid * 64 + 32 + lane] = make_float2(a2, a3);   // cols 64+2l, 65+2l
    }
    __syncthreads();
    if (tid < 128) {
        float g = 0.f;
        #pragma unroll
        for (int w = 0; w < 16; w++) g += red[w * 128 + tid];
        g_gePart[blockIdx.x * 128 + tid] = g;
    }
    if (tid < 32) {
        float s2 = wrow[tid] + wrow[tid + 32] + wrow[tid + 64] + wrow[tid + 96];
        #pragma unroll
        for (int off = 16; off; off >>= 1) s2 += __shfl_xor_sync(0xffffffffu, s2, off);
        if (tid == 0) g_esumPart[blockIdx.x] = s2;
    }
    __syncthreads();
    if (wid == 0) TCGEN05_DEALLOC(tmem_base, 256);

#else
    // ======================= FFMA2 fallback path =======================
    float* As = (float*)(smc + FF_AS);     // [128 m][128 k]
    float* Bs = (float*)(smc + FF_BS);     // [128 k][256 n]
    int tx = lane;                          // cols: j = 64*np + 2*tx (+1)
    int ty = wid;                           // rows: ty*8 .. ty*8+7

    {
        const float4* E4 = (const float4*)E + rowbase * 32;
        float4* As4 = (float4*)As;
        #pragma unroll
        for (int it = 0; it < 8; it++) As4[tid + it * 512] = E4[tid + it * 512];
        const float4* Wt4 = (const float4*)g_Wt;
        float4* Bs4 = (float4*)Bs;
        #pragma unroll
        for (int it = 0; it < 16; it++) Bs4[tid + it * 512] = Wt4[tid + it * 512];
    }
    if (tid < 128) {
        cvecS[tid] = g_Cvec[tid];
        biasS[tid] = g_bias[tid];
        wvcS[tid]  = wvc[tid];
        esm[tid]   = g_e[rowbase + tid];
        spm[tid]   = g_sp[rowbase + tid];
    }
    float Sv  = g_S;
    float bvc = bvcp[0];
    __syncthreads();

    u64 acc[8][4];
    #pragma unroll
    for (int mm = 0; mm < 8; mm++)
        #pragma unroll
        for (int np = 0; np < 4; np++) acc[mm][np] = 0ull;

    const float* Arow = As + (ty * 8) * 128;
    #pragma unroll 2
    for (int k0 = 0; k0 < 128; k0 += 2) {
        float2 a2[8];
        #pragma unroll
        for (int mm = 0; mm < 8; mm++)
            a2[mm] = *(const float2*)(Arow + mm * 128 + k0);   // warp-broadcast
        const u64* b0p = (const u64*)(Bs) + (u64)k0 * 128 + tx;
        const u64* b1p = b0p + 128;
        u64 b0[4], b1[4];
        #pragma unroll
        for (int np = 0; np < 4; np++) { b0[np] = b0p[np * 32]; b1[np] = b1p[np * 32]; }
        #pragma unroll
        for (int mm = 0; mm < 8; mm++) {
            u64 ad = pack2(a2[mm].x, a2[mm].x);
            #pragma unroll
            for (int np = 0; np < 4; np++) fma2(acc[mm][np], ad, b0[np]);
        }
        #pragma unroll
        for (int mm = 0; mm < 8; mm++) {
            u64 ad = pack2(a2[mm].y, a2[mm].y);
            #pragma unroll
            for (int np = 0; np < 4; np++) fma2(acc[mm][np], ad, b1[np]);
        }
    }

    // register epilogue: a-col j = 64*np+2tx pairs with b-col j+128 = np+2 in same thread
    #pragma unroll
    for (int rr = 0; rr < 8; rr++) {
        int r = ty * 8 + rr;
        float e_i = esm[r];
        float inv = 1.0f / (Sv - e_i);
        float accp = 0.f;
        #pragma unroll
        for (int np = 0; np < 2; np++) {
            float ax, ay, bx, by;
            unpack2(acc[rr][np], ax, ay);
            unpack2(acc[rr][np + 2], bx, by);
            int j = 64 * np + 2 * tx;
            float hx = ax + (cvecS[j]     - e_i * bx) * inv + biasS[j];
            float hy = ay + (cvecS[j + 1] - e_i * by) * inv + biasS[j + 1];
            accp += fmaxf(hx, 0.f) * wvcS[j] + fmaxf(hy, 0.f) * wvcS[j + 1];
        }
        #pragma unroll
        for (int off = 16; off; off >>= 1) accp += __shfl_xor_sync(0xffffffffu, accp, off);
        if (tx == 0) {
            float lg = spm[r] + accp + bvc;
            float wv = expf(lg);
            wrow[r] = wv;
            g_expw[rowbase + r] = wv;
        }
    }
    __syncthreads();

    {
        int d = tid & 127;
        int grp = tid >> 7;          // 0..3 -> 32 rows each
        float g = 0.f;
        #pragma unroll 8
        for (int rr = 0; rr < 32; rr++) {
            int r = grp * 32 + rr;
            g = fmaf(wrow[r], As[r * 128 + d], g);
        }
        red[grp * 128 + d] = g;
    }
    __syncthreads();
    if (tid < 128)
        g_gePart[blockIdx.x * 128 + tid] =
            red[tid] + red[128 + tid] + red[256 + tid] + red[384 + tid];
    if (tid < 32) {
        float s2 = wrow[tid] + wrow[tid + 32] + wrow[tid + 64] + wrow[tid + 96];
        #pragma unroll
        for (int off = 16; off; off >>= 1) s2 += __shfl_xor_sync(0xffffffffu, s2, off);
        if (tid == 0) g_esumPart[blockIdx.x] = s2;
    }
#endif
}

// ---------------- kernel 4a: reduce 2048 block partials -> 32 ----------------
__global__ void k4a_reduce() {
    int b0 = blockIdx.x * 64;
    int d = threadIdx.x;    // 128 threads
    float g = 0.f;
    #pragma unroll 8
    for (int j = 0; j < 64; j++) g += g_gePart[(b0 + j) * 128 + d];
    g_ge2[blockIdx.x * 128 + d] = g;
    if (d == 0) {
        float s = 0.f;
        for (int j = 0; j < 64; j++) s += g_esumPart[b0 + j];
        g_esum2[blockIdx.x] = s;
    }
}

// ---------------- kernel 4b: final ge + total ----------------
__global__ void k4b_final(float* ge_out) {
    __shared__ float tot;
    int d = threadIdx.x;    // 128 threads
    float g = 0.f;
    #pragma unroll
    for (int c = 0; c < 32; c++) g += g_ge2[c * 128 + d];
    if (d < 32) {
        float t = g_esum2[d];
        #pragma unroll
        for (int off = 16; off; off >>= 1) t += __shfl_xor_sync(0xffffffffu, t, off);
        if (d == 0) { tot = t; g_total = t; }
    }
    __syncthreads();
    if (ge_out) ge_out[d] = g / tot;
}

// ---------------- kernel 5: attention weights ----------------
__global__ void k5_attn(float* __restrict__ attn_out) {
    int i = blockIdx.x * 1024 + threadIdx.x;
    attn_out[i] = g_expw[i] / g_total;
}

// ---------------- launcher ----------------
extern "C" void kernel_launch(void* const* d_in, const int* in_sizes, int n_in,
                              void* d_out, int out_size) {
    const float* E    = (const float*)d_in[0];
    const float* item = (const float*)d_in[1];
    const float* W1   = (const float*)d_in[2];
    const float* bc1  = (const float*)d_in[3];
    const float* W2   = (const float*)d_in[4];
    const float* bc2  = (const float*)d_in[5];
    const float* wpa  = (const float*)d_in[6];
    const float* bpa  = (const float*)d_in[7];
    const float* wvc  = (const float*)d_in[8];
    const float* bvc  = (const float*)d_in[9];

    float* out = (float*)d_out;
    float* ge_out = nullptr;
    float* attn_out = nullptr;
    if (out_size == NROWS + DDIM)      { ge_out = out; attn_out = out + DDIM; }
    else if (out_size == DDIM)         { ge_out = out; }
    else                               { attn_out = out; }

    cudaFuncSetAttribute(k1_pass1, cudaFuncAttributeMaxDynamicSharedMemorySize, K1_BYTES);
    cudaFuncSetAttribute(k3_main,  cudaFuncAttributeMaxDynamicSharedMemorySize, SM3_BYTES);

    k0_wt<<<128, 256>>>(W1, W2);
    k0b_bimg<<<64, 256>>>(W1, W2);
    k1_pass1<<<2048, 128, K1_BYTES>>>(E, item, wpa, bpa);
    k2_reduce<<<1, 256>>>(W2, bc1, bc2);
    k3_main<<<2048, 512, SM3_BYTES>>>(E, wvc, bvc);
    k4a_reduce<<<32, 128>>>();
    k4b_final<<<1, 128>>>(ge_out);
    if (attn_out) k5_attn<<<256, 1024>>>(attn_out);
}

// round 6
// speedup vs baseline: 1.7104x; 1.7104x over previous
#include <cuda_runtime.h>
#include <cuda_bf16.h>
#include <cstdint>

#define NROWS 262144
#define DDIM  128

typedef unsigned long long u64;
typedef unsigned int u32;

#if defined(__CUDA_ARCH__) && defined(__CUDA_ARCH_FEAT_SM103_ALL)
#define HAS_TCGEN05 1
#else
#define HAS_TCGEN05 0
#endif

// ---------------- device scratch (no allocations allowed) ----------------
__device__ float g_e[NROWS];
__device__ float g_sp[NROWS];
__device__ float g_expw[NROWS];
__device__ float g_S_part[2048];
__device__ float g_sumeE_part[2048 * 128];
__device__ float g_seMid[128 * 128];
__device__ float g_SMid[128];
__device__ float g_S;
__device__ float g_Cvec[128];
__device__ float g_bias[128];
__device__ __align__(16) float g_Wt[128 * 256];  // Wt[k][n] fp32 (FFMA2 path)
__device__ __align__(16) u32 g_Bhi_img[16384];   // pre-swizzled bf16 hi image (tcgen05 path)
__device__ __align__(16) u32 g_Blo_img[16384];   // pre-swizzled bf16 lo image
__device__ float g_gePart[2048 * 128];
__device__ float g_esumPart[2048];
__device__ float g_ge2[32 * 128];
__device__ float g_esum2[32];
__device__ float g_total;

// ---------------- generic helpers ----------------
#define SMEM_SW128(o) ((o) ^ (((o) >> 3) & 0x70))

__device__ __forceinline__ u64 pack2(float x, float y) {
    u64 r;
    asm("mov.b64 %0, {%1, %2};" : "=l"(r) : "f"(x), "f"(y));
    return r;
}
__device__ __forceinline__ void fma2(u64 &d, u64 a, u64 b) {
    asm("fma.rn.f32x2 %0, %1, %2, %0;" : "+l"(d) : "l"(a), "l"(b));
}
__device__ __forceinline__ void unpack2(u64 v, float &x, float &y) {
    asm("mov.b64 {%0, %1}, %2;" : "=f"(x), "=f"(y) : "l"(v));
}

// ---------------- smem layout for k3 (shared by both paths) ----------------
#define FF_AS     0          // 128x128 fp32  (65536 B)
#define FF_BS     65536      // 128x256 fp32  (131072 B)
#define A_HI_OFF  0          // tcgen05 path: bf16 images
#define A_LO_OFF  32768
#define B_HI_OFF  65536
#define B_LO_OFF  131072
#define TMEMPTR_OFF 196608
#define MBAR_OFF    196616
#define CVEC_OFF    196640
#define BIAS_OFF    197152
#define WVC_OFF     197664
#define ESM_OFF     198176
#define SPM_OFF     198688
#define WROW_OFF    199200
#define RED_OFF     199712   // up to 8192 B
#define SM3_BYTES   208896

// ---------------- kernel 0: build Wt[k][n] = [W1^T | W2^T] (fp32) ----------------
__global__ void k0_wt(const float* __restrict__ W1, const float* __restrict__ W2) {
    int idx = blockIdx.x * 256 + threadIdx.x;   // 0..32767
    int k = idx >> 8;
    int n = idx & 255;
    g_Wt[idx] = (n < 128) ? W1[n * 128 + k] : W2[(n - 128) * 128 + k];
}

// ---------------- kernel 0b: pre-swizzled bf16 hi/lo B image (tcgen05 path) ----------------
__global__ void k0b_bimg(const float* __restrict__ W1, const float* __restrict__ W2) {
    int idx = blockIdx.x * 256 + threadIdx.x;    // 0..16383 bf16x2 words
    int n = idx >> 6;
    int kp = (idx & 63) * 2;
    const float* src = (n < 128) ? (W1 + n * 128) : (W2 + (n - 128) * 128);
    float x0 = src[kp], x1 = src[kp + 1];
    __nv_bfloat16 h0 = __float2bfloat16_rn(x0);
    __nv_bfloat16 h1 = __float2bfloat16_rn(x1);
    __nv_bfloat162 hw = __nv_bfloat162(h0, h1);
    __nv_bfloat162 lw = __floats2bfloat162_rn(x0 - __bfloat162float(h0),
                                              x1 - __bfloat162float(h1));
    int off = ((n >> 3) + (kp >> 6) * 32) * 1024 + (n & 7) * 128 + (kp & 63) * 2;
    int sw = SMEM_SW128(off);
    g_Bhi_img[sw >> 2] = *(u32*)&hw;
    g_Blo_img[sw >> 2] = *(u32*)&lw;
}

// ---------------- kernel 1: sp, s->e, partial S, partial sum_eE (smem-staged) ----------------
#define K1_STRIDE 129
#define K1_SVW    (128 * K1_STRIDE)
#define K1_EXP    (K1_SVW + 256)
#define K1_FLOATS (K1_EXP + 128)
#define K1_BYTES  (K1_FLOATS * 4)

__global__ __launch_bounds__(128) void k1_pass1(const float* __restrict__ E,
                                                const float* __restrict__ v,
                                                const float* __restrict__ wpa,
                                                const float* __restrict__ bpa) {
    extern __shared__ float s1[];
    float*  Es  = s1;
    float2* svw = (float2*)(s1 + K1_SVW);
    float*  es  = s1 + K1_EXP;

    int t = threadIdx.x;
    int rowbase = blockIdx.x * 128;
    const float4* E4 = (const float4*)E + rowbase * 32;

    #pragma unroll
    for (int i = 0; i < 32; i++) {
        int g4 = t + i * 128;
        int r = g4 >> 5, c4 = g4 & 31;
        float4 val = E4[g4];
        Es[(c4 * 4 + 0) * K1_STRIDE + r] = val.x;
        Es[(c4 * 4 + 1) * K1_STRIDE + r] = val.y;
        Es[(c4 * 4 + 2) * K1_STRIDE + r] = val.z;
        Es[(c4 * 4 + 3) * K1_STRIDE + r] = val.w;
    }
    svw[t] = make_float2(wpa[t], v[t]);
    __syncthreads();

    float sp = 0.f, s = 0.f;
    #pragma unroll 8
    for (int k = 0; k < 128; k++) {
        float ev = Es[k * K1_STRIDE + t];
        float2 c = svw[k];
        s  = fmaf(ev, c.x, s);
        sp = fmaf(ev, c.y, sp);
    }
    s += bpa[0];
    float e = expf(s);       // softmax shift-invariant; exponents tiny
    g_sp[rowbase + t] = sp;
    g_e[rowbase + t]  = e;
    es[t] = e;
    __syncthreads();

    float acc = 0.f;
    #pragma unroll 8
    for (int r = 0; r < 128; r++) acc = fmaf(es[r], Es[t * K1_STRIDE + r], acc);
    g_sumeE_part[blockIdx.x * 128 + t] = acc;

    if (t < 32) {
        float t4 = es[t] + es[t + 32] + es[t + 64] + es[t + 96];
        #pragma unroll
        for (int off = 16; off; off >>= 1) t4 += __shfl_xor_sync(0xffffffffu, t4, off);
        if (t == 0) g_S_part[blockIdx.x] = t4;
    }
}

// ---------------- kernel 2a: parallel fold 2048 partials -> 128 ----------------
__global__ __launch_bounds__(128) void k2a_reduce() {
    int b = blockIdx.x;      // 0..127
    int d = threadIdx.x;     // 0..127
    float p = 0.f;
    #pragma unroll
    for (int j = 0; j < 16; j++) p += g_sumeE_part[(b * 16 + j) * 128 + d];
    g_seMid[b * 128 + d] = p;
    if (d == 0) {
        float s = 0.f;
        #pragma unroll
        for (int j = 0; j < 16; j++) s += g_S_part[b * 16 + j];
        g_SMid[b] = s;
    }
}

// ---------------- kernel 2b: final fold; Cvec = W2 @ sum_eE; bias; S ----------------
__global__ __launch_bounds__(128) void k2b_reduce(const float* __restrict__ W2,
                                                  const float* __restrict__ b_c1,
                                                  const float* __restrict__ b_c2) {
    __shared__ float se[128];
    int d = threadIdx.x;
    float p = 0.f;
    #pragma unroll 8
    for (int j = 0; j < 128; j++) p += g_seMid[j * 128 + d];
    se[d] = p;
    if (d < 32) {
        float s = g_SMid[d] + g_SMid[d + 32] + g_SMid[d + 64] + g_SMid[d + 96];
        #pragma unroll
        for (int off = 16; off; off >>= 1) s += __shfl_xor_sync(0xffffffffu, s, off);
        if (d == 0) g_S = s;
    }
    __syncthreads();
    float c = 0.f;
    #pragma unroll 8
    for (int k = 0; k < 128; k++) c = fmaf(W2[d * 128 + k], se[k], c);
    g_Cvec[d] = c;
    g_bias[d] = b_c1[d] + b_c2[d];
}

// ---------------- tcgen05 helpers (only compiled on 103a feature pass) ----------------
#if HAS_TCGEN05
__device__ __forceinline__ u32 smem_to_u32(const void* p) {
    u32 a;
    asm("{ .reg .u64 t; cvta.to.shared.u64 t, %1; cvt.u32.u64 %0, t; }" : "=r"(a) : "l"(p));
    return a;
}
__device__ __forceinline__ u32 elect_one_pred() {
    u32 pred;
    asm volatile("{ .reg .pred p; elect.sync _|p, 0xFFFFFFFF; selp.b32 %0, 1, 0, p; }" : "=r"(pred));
    return pred;
}
static constexpr u64 SMEM_DESC_BASE_SW128 =
    (u64(2) << 61) | (u64(1) << 46) | (u64(64) << 32) | (u64(1) << 16);
#define MAKE_SMEM_DESC(a) (SMEM_DESC_BASE_SW128 | ((u64)((a) >> 4) & 0x3FFF))

#define TCGEN05_ALLOC(sa, n) \
    asm volatile("tcgen05.alloc.cta_group::1.sync.aligned.shared::cta.b32 [%0], %1;" \
                 :: "r"((u32)(sa)), "r"((u32)(n)) : "memory")
#define TCGEN05_DEALLOC(t, n) \
    asm volatile("tcgen05.dealloc.cta_group::1.sync.aligned.b32 %0, %1;" :: "r"(t), "r"((u32)(n)))
#define TCGEN05_COMMIT(mb) \
    asm volatile("tcgen05.commit.cta_group::1.mbarrier::arrive::one.shared::cluster.b64 [%0];" \
                 :: "r"((u32)(mb)) : "memory")
#define TCGEN05_WAIT_LD()  asm volatile("tcgen05.wait::ld.sync.aligned;" ::: "memory")
#define TCGEN05_FENCE_AFTER() asm volatile("tcgen05.fence::after_thread_sync;" ::: "memory")
#define TCGEN05_FENCE_BEFORE() asm volatile("tcgen05.fence::before_thread_sync;" ::: "memory")
#define MBARRIER_INIT(mb, c) \
    asm volatile("mbarrier.init.shared.b64 [%0], %1;" :: "r"((u32)(mb)), "r"((u32)(c)) : "memory")
#define MBARRIER_WAIT_PARITY(mb, ph) do { \
    u32 _mb = (u32)(mb); u32 _p = (u32)(ph); u32 _done; \
    asm volatile("{ .reg .pred p; mbarrier.try_wait.parity.acquire.cta.shared::cta.b64 p, [%1], %2; selp.b32 %0, 1, 0, p; }" \
        : "=r"(_done) : "r"(_mb), "r"(_p) : "memory"); \
    if (!_done) { \
        asm volatile("{ .reg .pred P1; WL_%=: mbarrier.try_wait.parity.acquire.cta.shared::cta.b64 P1, [%0], %1, 0x989680; @P1 bra.uni WD_%=; bra.uni WL_%=; WD_%=: }" \
            :: "r"(_mb), "r"(_p) : "memory"); \
    } \
} while (0)
#define TCGEN05_LD_32X32B_X32(r, ta) \
    asm volatile("tcgen05.ld.sync.aligned.32x32b.x32.b32 " \
        "{%0, %1, %2, %3, %4, %5, %6, %7, %8, %9, %10, %11, %12, %13, %14, %15, " \
        " %16, %17, %18, %19, %20, %21, %22, %23, %24, %25, %26, %27, %28, %29, %30, %31}, [%32];" \
        : "=r"((r)[0]),  "=r"((r)[1]),  "=r"((r)[2]),  "=r"((r)[3]), \
          "=r"((r)[4]),  "=r"((r)[5]),  "=r"((r)[6]),  "=r"((r)[7]), \
          "=r"((r)[8]),  "=r"((r)[9]),  "=r"((r)[10]), "=r"((r)[11]), \
          "=r"((r)[12]), "=r"((r)[13]), "=r"((r)[14]), "=r"((r)[15]), \
          "=r"((r)[16]), "=r"((r)[17]), "=r"((r)[18]), "=r"((r)[19]), \
          "=r"((r)[20]), "=r"((r)[21]), "=r"((r)[22]), "=r"((r)[23]), \
          "=r"((r)[24]), "=r"((r)[25]), "=r"((r)[26]), "=r"((r)[27]), \
          "=r"((r)[28]), "=r"((r)[29]), "=r"((r)[30]), "=r"((r)[31]) \
        : "r"(ta))

__device__ __forceinline__ void mma_f16_ss(u32 d, u64 ad, u64 bd, u32 idesc, bool en) {
    u32 e = en ? 1u : 0u;
    asm volatile(
        "{\n\t.reg .pred p;\n\tsetp.ne.u32 p, %4, 0;\n\t"
        "tcgen05.mma.cta_group::1.kind::f16 [%0], %1, %2, %3, {%5, %5, %5, %5}, p;\n\t}"
        :: "r"(d), "l"(ad), "l"(bd), "r"(idesc), "r"(e), "r"(0u) : "memory");
}
static constexpr u32 MMA_IDESC_N128 =
    (1u << 4) | (1u << 7) | (1u << 10) | (16u << 17) | (8u << 24);
#endif  // HAS_TCGEN05

// ---------------- kernel 3: main fused GEMM + PI + logits + block partials ----------------
// 2048 blocks x 512 threads; 128 rows/block; N=256; K=128.
__global__ __launch_bounds__(512, 1)
void k3_main(const float* __restrict__ E,
             const float* __restrict__ wvc,
             const float* __restrict__ bvcp) {
    extern __shared__ char smc[];
    float* cvecS = (float*)(smc + CVEC_OFF);
    float* biasS = (float*)(smc + BIAS_OFF);
    float* wvcS  = (float*)(smc + WVC_OFF);
    float* esm   = (float*)(smc + ESM_OFF);
    float* spm   = (float*)(smc + SPM_OFF);
    float* wrow  = (float*)(smc + WROW_OFF);
    float* red   = (float*)(smc + RED_OFF);

    int tid = threadIdx.x;
    int lane = tid & 31;
    int wid = tid >> 5;             // 0..15
    int rowbase = blockIdx.x * 128;

#if HAS_TCGEN05
    // ======================= tcgen05 path =======================
    u32 smem_base = smem_to_u32(smc);
    if (wid == 0) TCGEN05_ALLOC(smem_base + TMEMPTR_OFF, 256);
    if (tid == 0) MBARRIER_INIT(smem_base + MBAR_OFF, 1);

    {   // copy pre-swizzled B images
        const float4* bh = (const float4*)g_Bhi_img;
        const float4* bl = (const float4*)g_Blo_img;
        float4* dh = (float4*)(smc + B_HI_OFF);
        float4* dl = (float4*)(smc + B_LO_OFF);
        #pragma unroll
        for (int i = 0; i < 8; i++) {
            dh[tid + i * 512] = bh[tid + i * 512];
            dl[tid + i * 512] = bl[tid + i * 512];
        }
    }
    {   // load E tile, split bf16 hi/lo, store swizzled
        const float4* E4 = (const float4*)E + rowbase * 32;
        #pragma unroll
        for (int i = 0; i < 8; i++) {
            int g4 = tid + i * 512;
            int r = g4 >> 5;
            int c = (g4 & 31) * 4;
            float4 x = E4[g4];
            __nv_bfloat16 h0 = __float2bfloat16_rn(x.x);
            __nv_bfloat16 h1 = __float2bfloat16_rn(x.y);
            __nv_bfloat16 h2 = __float2bfloat16_rn(x.z);
            __nv_bfloat16 h3 = __float2bfloat16_rn(x.w);
            __nv_bfloat162 hw0 = __nv_bfloat162(h0, h1);
            __nv_bfloat162 hw1 = __nv_bfloat162(h2, h3);
            __nv_bfloat162 lw0 = __floats2bfloat162_rn(x.x - __bfloat162float(h0),
                                                       x.y - __bfloat162float(h1));
            __nv_bfloat162 lw1 = __floats2bfloat162_rn(x.z - __bfloat162float(h2),
                                                       x.w - __bfloat162float(h3));
            int off = ((r >> 3) + (c >> 6) * 16) * 1024 + (r & 7) * 128 + (c & 63) * 2;
            int sw = SMEM_SW128(off);
            u64 hp = (u64)(*(u32*)&hw0) | ((u64)(*(u32*)&hw1) << 32);
            u64 lp = (u64)(*(u32*)&lw0) | ((u64)(*(u32*)&lw1) << 32);
            *(u64*)(smc + A_HI_OFF + sw) = hp;
            *(u64*)(smc + A_LO_OFF + sw) = lp;
        }
    }
    if (tid < 128) {
        cvecS[tid] = g_Cvec[tid];
        biasS[tid] = g_bias[tid];
        wvcS[tid]  = wvc[tid];
        esm[tid]   = g_e[rowbase + tid];
        spm[tid]   = g_sp[rowbase + tid];
    }
    float Sv  = g_S;
    float bvc = bvcp[0];

    asm volatile("fence.proxy.async.shared::cta;" ::: "memory");
    __syncthreads();
    u32 tmem_base;
    asm volatile("ld.shared.b32 %0, [%1];" : "=r"(tmem_base) : "r"(smem_base + TMEMPTR_OFF));

    if (wid == 0) {
        if (elect_one_pred()) {
            u64 adh = MAKE_SMEM_DESC(smem_base + A_HI_OFF);
            u64 adl = MAKE_SMEM_DESC(smem_base + A_LO_OFF);
            u64 bdh = MAKE_SMEM_DESC(smem_base + B_HI_OFF);
            u64 bdl = MAKE_SMEM_DESC(smem_base + B_LO_OFF);
            const u64 aoff[8] = {0, 2, 4, 6, 1024, 1026, 1028, 1030};
            const u64 boff[8] = {0, 2, 4, 6, 2048, 2050, 2052, 2054};
            #pragma unroll
            for (int nh = 0; nh < 2; nh++) {
                u32 dtm = tmem_base + nh * 128;
                u64 bh = bdh + nh * 1024;
                u64 bl = bdl + nh * 1024;
                #pragma unroll
                for (int s = 0; s < 8; s++)
                    mma_f16_ss(dtm, adh + aoff[s], bh + boff[s], MMA_IDESC_N128, s > 0);
                #pragma unroll
                for (int s = 0; s < 8; s++)
                    mma_f16_ss(dtm, adh + aoff[s], bl + boff[s], MMA_IDESC_N128, true);
                #pragma unroll
                for (int s = 0; s < 8; s++)
                    mma_f16_ss(dtm, adl + aoff[s], bh + boff[s], MMA_IDESC_N128, true);
            }
            TCGEN05_COMMIT(smem_base + MBAR_OFF);
        }
    }

    MBARRIER_WAIT_PARITY(smem_base + MBAR_OFF, 0);
    TCGEN05_FENCE_AFTER();

    if (wid < 4) {
        int r = wid * 32 + lane;
        float e_i = esm[r];
        float inv = 1.0f / (Sv - e_i);
        float pi = 0.f;
        #pragma unroll
        for (int q = 0; q < 4; q++) {
            u32 ra[32], rb[32];
            TCGEN05_LD_32X32B_X32(ra, tmem_base + q * 32);
            TCGEN05_LD_32X32B_X32(rb, tmem_base + 128 + q * 32);
            TCGEN05_WAIT_LD();
            #pragma unroll
            for (int jj = 0; jj < 32; jj++) {
                int j = q * 32 + jj;
                float a  = __uint_as_float(ra[jj]);
                float bb = __uint_as_float(rb[jj]);
                float hv = a + (cvecS[j] - e_i * bb) * inv + biasS[j];
                pi += fmaxf(hv, 0.f) * wvcS[j];
            }
        }
        TCGEN05_FENCE_BEFORE();
        float lg = spm[r] + pi + bvc;
        float wv = expf(lg);
        wrow[r] = wv;
        g_expw[rowbase + r] = wv;
    }
    __syncthreads();

    {
        float a0 = 0.f, a1 = 0.f, a2 = 0.f, a3 = 0.f;
        #pragma unroll
        for (int rr = 0; rr < 8; rr++) {
            int r = wid * 8 + rr;
            float wv = wrow[r];
            int base = (r >> 3) * 1024 + (r & 7) * 128;
            int o0 = SMEM_SW128(base + lane * 4);
            int o1 = SMEM_SW128(base + 16 * 1024 + lane * 4);
            float2 h0 = __bfloat1622float2(*(const __nv_bfloat162*)(smc + A_HI_OFF + o0));
            float2 l0 = __bfloat1622float2(*(const __nv_bfloat162*)(smc + A_LO_OFF + o0));
            float2 h1 = __bfloat1622float2(*(const __nv_bfloat162*)(smc + A_HI_OFF + o1));
            float2 l1 = __bfloat1622float2(*(const __nv_bfloat162*)(smc + A_LO_OFF + o1));
            a0 = fmaf(wv, h0.x + l0.x, a0);
            a1 = fmaf(wv, h0.y + l0.y, a1);
            a2 = fmaf(wv, h1.x + l1.x, a2);
            a3 = fmaf(wv, h1.y + l1.y, a3);
        }
        float2* r2 = (float2*)red;
        r2[wid * 64 + lane]      = make_float2(a0, a1);
        r2[wid * 64 + 32 + lane] = make_float2(a2, a3);
    }
    __syncthreads();
    if (tid < 128) {
        float g = 0.f;
        #pragma unroll
        for (int w = 0; w < 16; w++) g += red[w * 128 + tid];
        g_gePart[blockIdx.x * 128 + tid] = g;
    }
    if (tid < 32) {
        float s2 = wrow[tid] + wrow[tid + 32] + wrow[tid + 64] + wrow[tid + 96];
        #pragma unroll
        for (int off = 16; off; off >>= 1) s2 += __shfl_xor_sync(0xffffffffu, s2, off);
        if (tid == 0) g_esumPart[blockIdx.x] = s2;
    }
    __syncthreads();
    if (wid == 0) TCGEN05_DEALLOC(tmem_base, 256);

#else
    // ======================= FFMA2 fallback path =======================
    float* As = (float*)(smc + FF_AS);     // [128 m][128 k]
    float* Bs = (float*)(smc + FF_BS);     // [128 k][256 n]
    int tx = lane;                          // cols: j = 64*np + 2*tx (+1)
    int ty = wid;                           // rows: ty*8 .. ty*8+7

    {
        const float4* E4 = (const float4*)E + rowbase * 32;
        float4* As4 = (float4*)As;
        #pragma unroll
        for (int it = 0; it < 8; it++) As4[tid + it * 512] = E4[tid + it * 512];
        const float4* Wt4 = (const float4*)g_Wt;
        float4* Bs4 = (float4*)Bs;
        #pragma unroll
        for (int it = 0; it < 16; it++) Bs4[tid + it * 512] = Wt4[tid + it * 512];
    }
    if (tid < 128) {
        cvecS[tid] = g_Cvec[tid];
        biasS[tid] = g_bias[tid];
        wvcS[tid]  = wvc[tid];
        esm[tid]   = g_e[rowbase + tid];
        spm[tid]   = g_sp[rowbase + tid];
    }
    float Sv  = g_S;
    float bvc = bvcp[0];
    __syncthreads();

    u64 acc[8][4];
    #pragma unroll
    for (int mm = 0; mm < 8; mm++)
        #pragma unroll
        for (int np = 0; np < 4; np++) acc[mm][np] = 0ull;

    const float* Arow = As + (ty * 8) * 128;
    #pragma unroll 2
    for (int k0 = 0; k0 < 128; k0 += 2) {
        float2 a2[8];
        #pragma unroll
        for (int mm = 0; mm < 8; mm++)
            a2[mm] = *(const float2*)(Arow + mm * 128 + k0);   // warp-broadcast
        const u64* b0p = (const u64*)(Bs) + (u64)k0 * 128 + tx;
        const u64* b1p = b0p + 128;
        u64 b0[4], b1[4];
        #pragma unroll
        for (int np = 0; np < 4; np++) { b0[np] = b0p[np * 32]; b1[np] = b1p[np * 32]; }
        #pragma unroll
        for (int mm = 0; mm < 8; mm++) {
            u64 ad = pack2(a2[mm].x, a2[mm].x);
            #pragma unroll
            for (int np = 0; np < 4; np++) fma2(acc[mm][np], ad, b0[np]);
        }
        #pragma unroll
        for (int mm = 0; mm < 8; mm++) {
            u64 ad = pack2(a2[mm].y, a2[mm].y);
            #pragma unroll
            for (int np = 0; np < 4; np++) fma2(acc[mm][np], ad, b1[np]);
        }
    }

    // register epilogue: a-col j = 64*np+2tx pairs with b-col j+128 = np+2 in same thread
    #pragma unroll
    for (int rr = 0; rr < 8; rr++) {
        int r = ty * 8 + rr;
        float e_i = esm[r];
        float inv = 1.0f / (Sv - e_i);
        float accp = 0.f;
        #pragma unroll
        for (int np = 0; np < 2; np++) {
            float ax, ay, bx, by;
            unpack2(acc[rr][np], ax, ay);
            unpack2(acc[rr][np + 2], bx, by);
            int j = 64 * np + 2 * tx;
            float hx = ax + (cvecS[j]     - e_i * bx) * inv + biasS[j];
            float hy = ay + (cvecS[j + 1] - e_i * by) * inv + biasS[j + 1];
            accp += fmaxf(hx, 0.f) * wvcS[j] + fmaxf(hy, 0.f) * wvcS[j + 1];
        }
        #pragma unroll
        for (int off = 16; off; off >>= 1) accp += __shfl_xor_sync(0xffffffffu, accp, off);
        if (tx == 0) {
            float lg = spm[r] + accp + bvc;
            float wv = expf(lg);
            wrow[r] = wv;
            g_expw[rowbase + r] = wv;
        }
    }
    __syncthreads();

    {
        int d = tid & 127;
        int grp = tid >> 7;          // 0..3 -> 32 rows each
        float g = 0.f;
        #pragma unroll 8
        for (int rr = 0; rr < 32; rr++) {
            int r = grp * 32 + rr;
            g = fmaf(wrow[r], As[r * 128 + d], g);
        }
        red[grp * 128 + d] = g;
    }
    __syncthreads();
    if (tid < 128)
        g_gePart[blockIdx.x * 128 + tid] =
            red[tid] + red[128 + tid] + red[256 + tid] + red[384 + tid];
    if (tid < 32) {
        float s2 = wrow[tid] + wrow[tid + 32] + wrow[tid + 64] + wrow[tid + 96];
        #pragma unroll
        for (int off = 16; off; off >>= 1) s2 += __shfl_xor_sync(0xffffffffu, s2, off);
        if (tid == 0) g_esumPart[blockIdx.x] = s2;
    }
#endif
}

// ---------------- kernel 4a: reduce 2048 block partials -> 32 ----------------
__global__ void k4a_reduce() {
    int b0 = blockIdx.x * 64;
    int d = threadIdx.x;    // 128 threads
    float g = 0.f;
    #pragma unroll 8
    for (int j = 0; j < 64; j++) g += g_gePart[(b0 + j) * 128 + d];
    g_ge2[blockIdx.x * 128 + d] = g;
    if (d == 0) {
        float s = 0.f;
        for (int j = 0; j < 64; j++) s += g_esumPart[b0 + j];
        g_esum2[blockIdx.x] = s;
    }
}

// ---------------- kernel 4b: final ge + total ----------------
__global__ void k4b_final(float* ge_out) {
    __shared__ float tot;
    int d = threadIdx.x;    // 128 threads
    float g = 0.f;
    #pragma unroll
    for (int c = 0; c < 32; c++) g += g_ge2[c * 128 + d];
    if (d < 32) {
        float t = g_esum2[d];
        #pragma unroll
        for (int off = 16; off; off >>= 1) t += __shfl_xor_sync(0xffffffffu, t, off);
        if (d == 0) { tot = t; g_total = t; }
    }
    __syncthreads();
    if (ge_out) ge_out[d] = g / tot;
}

// ---------------- kernel 5: attention weights ----------------
__global__ void k5_attn(float* __restrict__ attn_out) {
    int i = blockIdx.x * 1024 + threadIdx.x;
    attn_out[i] = g_expw[i] / g_total;
}

// ---------------- launcher ----------------
extern "C" void kernel_launch(void* const* d_in, const int* in_sizes, int n_in,
                              void* d_out, int out_size) {
    const float* E    = (const float*)d_in[0];
    const float* item = (const float*)d_in[1];
    const float* W1   = (const float*)d_in[2];
    const float* bc1  = (const float*)d_in[3];
    const float* W2   = (const float*)d_in[4];
    const float* bc2  = (const float*)d_in[5];
    const float* wpa  = (const float*)d_in[6];
    const float* bpa  = (const float*)d_in[7];
    const float* wvc  = (const float*)d_in[8];
    const float* bvc  = (const float*)d_in[9];

    float* out = (float*)d_out;
    float* ge_out = nullptr;
    float* attn_out = nullptr;
    if (out_size == NROWS + DDIM)      { ge_out = out; attn_out = out + DDIM; }
    else if (out_size == DDIM)         { ge_out = out; }
    else                               { attn_out = out; }

    cudaFuncSetAttribute(k1_pass1, cudaFuncAttributeMaxDynamicSharedMemorySize, K1_BYTES);
    cudaFuncSetAttribute(k3_main,  cudaFuncAttributeMaxDynamicSharedMemorySize, SM3_BYTES);

    k0_wt<<<128, 256>>>(W1, W2);
    k0b_bimg<<<64, 256>>>(W1, W2);
    k1_pass1<<<2048, 128, K1_BYTES>>>(E, item, wpa, bpa);
    k2a_reduce<<<128, 128>>>();
    k2b_reduce<<<1, 128>>>(W2, bc1, bc2);
    k3_main<<<2048, 512, SM3_BYTES>>>(E, wvc, bvc);
    k4a_reduce<<<32, 128>>>();
    k4b_final<<<1, 128>>>(ge_out);
    if (attn_out) k5_attn<<<256, 1024>>>(attn_out);
}